// round 8
// baseline (speedup 1.0000x reference)
#include <cuda_runtime.h>
#include <cuda_fp16.h>

#define SEQ    8192
#define DIN    256
#define H      2048
#define FOURH  8192
#define DOUT   64
#define GRID_LSTM 148
#define NTHREADS  256

#define KREG   14            // half2 chunks per row held in registers
#define KSMEM  (32 - KREG)   // half2 chunks per row held in SMEM

// ---- static scratch (no allocations allowed) ----
__device__ __align__(16) float g_xg[(size_t)SEQ * FOURH];   // 256 MB
__device__ __align__(16) float g_hs[(size_t)SEQ * H];       // 64 MB
// tagged h exchange: word = (step_tag << 16) | fp16(h). double-buffered by parity.
__device__ __align__(16) unsigned g_htag[2][H];

// SMEM layout (bytes)
#define WSM_BYTES (56 * KSMEM * 32 * 4)
#define HSM_OFF   WSM_BYTES
#define ZBUF_OFF  (HSM_OFF + 4096)
#define CBUF_OFF  (ZBUF_OFF + 256)
#define LSTM_SMEM (CBUF_OFF + 64)

__device__ __forceinline__ float ftanh(float x) {
    float ax = fabsf(x);
    float e = __expf(-2.f * ax);
    float r = (1.f - e) / (1.f + e);
    return copysignf(r, x);
}
__device__ __forceinline__ float fsigmoid(float x) {
    return 1.f / (1.f + __expf(-x));
}
__device__ __forceinline__ unsigned ld_rlx(const unsigned* p) {
    unsigned v;
    asm volatile("ld.relaxed.gpu.global.u32 %0, [%1];" : "=r"(v) : "l"(p));
    return v;
}
__device__ __forceinline__ void st_rlx(unsigned* p, unsigned v) {
    asm volatile("st.relaxed.gpu.global.u32 [%0], %1;" :: "l"(p), "r"(v));
}

// ============================================================
// Kernel 1: xg[t, r] = x[t,:] . W_ih[r,:] + (b_ih[r]+b_hh[r])
// Block (0,0) also resets the tag scratch for this replay.
// ============================================================
__global__ void xg_gemm(const float* __restrict__ x, const float* __restrict__ Wih,
                        const float* __restrict__ bih, const float* __restrict__ bhh) {
    __shared__ float sA[64][65];
    __shared__ float sB[64][65];
    const int bm = blockIdx.y * 64;
    const int bn = blockIdx.x * 64;
    const int tid = threadIdx.x;
    const int tm = tid & 15, tn = tid >> 4;

    if (blockIdx.x == 0 && blockIdx.y == 0) {
        for (int i = tid; i < 2 * H; i += 256) ((unsigned*)g_htag)[i] = 0u;
    }

    float acc[4][4];
#pragma unroll
    for (int i = 0; i < 4; i++)
#pragma unroll
        for (int j = 0; j < 4; j++) acc[i][j] = 0.f;

    for (int kc = 0; kc < DIN; kc += 64) {
#pragma unroll
        for (int i = 0; i < 16; i++) {
            int e = tid + i * 256;
            int row = e >> 6, col = e & 63;
            sA[col][row] = x[(size_t)(bm + row) * DIN + kc + col];
            sB[col][row] = Wih[(size_t)(bn + row) * DIN + kc + col];
        }
        __syncthreads();
#pragma unroll 16
        for (int kk = 0; kk < 64; kk++) {
            float a[4], b[4];
#pragma unroll
            for (int i = 0; i < 4; i++) a[i] = sA[kk][tm * 4 + i];
#pragma unroll
            for (int j = 0; j < 4; j++) b[j] = sB[kk][tn * 4 + j];
#pragma unroll
            for (int i = 0; i < 4; i++)
#pragma unroll
                for (int j = 0; j < 4; j++) acc[i][j] += a[i] * b[j];
        }
        __syncthreads();
    }
#pragma unroll
    for (int j = 0; j < 4; j++) {
        int n = bn + tn * 4 + j;
        float bias = bih[n] + bhh[n];
#pragma unroll
        for (int i = 0; i < 4; i++) {
            int m = bm + tm * 4 + i;
            g_xg[(size_t)m * FOURH + n] = acc[i][j] + bias;
        }
    }
}

// ============================================================
// Kernel 2: persistent LSTM recurrence.
// Sync: NONE. Tagged h words are polled directly by consumers with
// __nanosleep backoff (prevents the LTS hot-line queue collapse).
// ============================================================
__global__ void __launch_bounds__(NTHREADS, 1)
lstm_kernel(const float* __restrict__ Whh, const float* __restrict__ hprev,
            const float* __restrict__ cprev,
            float* __restrict__ out_hT, float* __restrict__ out_cT) {
    extern __shared__ char smem[];
    __half2* wsm  = (__half2*)smem;                    // [56][KSMEM][32]
    __half*  hsm  = (__half*)(smem + HSM_OFF);         // 2048 halves
    __half2* hsm2 = (__half2*)hsm;
    unsigned* hsmw = (unsigned*)hsm;
    float*   zbuf = (float*)(smem + ZBUF_OFF);
    float*   cbuf = (float*)(smem + CBUF_OFF);

    const int cta = blockIdx.x;
    const int tid = threadIdx.x;
    const int warp = tid >> 5, lane = tid & 31;
    const int ucount = (cta < 124) ? 14 : 13;
    const int ustart = (cta < 124) ? 14 * cta : (1736 + 13 * (cta - 124));
    const int nrows = 4 * ucount;

    // ---- one-time: load owned W_hh rows (fp16). reg part + SMEM part ----
    __half2 wreg[7][KREG];
#pragma unroll
    for (int r = 0; r < 7; r++) {
        int lr = warp * 7 + r;
        bool valid = lr < nrows;
        int u = lr >> 2, g = lr & 3;
        const float* wp = Whh + (size_t)(g * H + ustart + u) * H;
#pragma unroll
        for (int k = 0; k < KREG; k++) {
            int c = lane + 32 * k;
            wreg[r][k] = valid ? __floats2half2_rn(wp[2 * c], wp[2 * c + 1])
                               : __floats2half2_rn(0.f, 0.f);
        }
#pragma unroll
        for (int k2 = 0; k2 < KSMEM; k2++) {
            int c = lane + 32 * (KREG + k2);
            wsm[(lr * KSMEM + k2) * 32 + lane] =
                valid ? __floats2half2_rn(wp[2 * c], wp[2 * c + 1])
                      : __floats2half2_rn(0.f, 0.f);
        }
    }
    __syncthreads();

    for (int t = 0; t < SEQ; t++) {
        // xg prefetch for owned units (independent of h -> overlaps the wait)
        float xg0 = 0.f, xg1 = 0.f, xg2 = 0.f, xg3 = 0.f;
        if (tid < ucount) {
            int j = ustart + tid;
            const float* xr = g_xg + (size_t)t * FOURH;
            xg0 = __ldg(xr + j);
            xg1 = __ldg(xr + H + j);
            xg2 = __ldg(xr + 2 * H + j);
            xg3 = __ldg(xr + 3 * H + j);
        }

        // ---- stage h(t) into SMEM: bulk read + tag-verify with backoff ----
        if (t == 0) {
#pragma unroll
            for (int i = 0; i < 8; i++)
                hsm[tid * 8 + i] = __float2half_rn(hprev[tid * 8 + i]);
        } else {
            const unsigned* src = &g_htag[t & 1][tid * 8];
            uint4 a = __ldcg((const uint4*)src);
            uint4 b = __ldcg((const uint4*)src + 1);
            unsigned w[8] = {a.x, a.y, a.z, a.w, b.x, b.y, b.z, b.w};
            const unsigned expect = (unsigned)t;
#pragma unroll
            for (int i = 0; i < 8; i++) {
                while ((w[i] >> 16) != expect) {
                    __nanosleep(60);          // backoff: keep LTS queues empty
                    w[i] = ld_rlx(src + i);
                }
            }
#pragma unroll
            for (int i = 0; i < 4; i++)
                hsmw[tid * 4 + i] = (w[2 * i] & 0xffffu) | (w[2 * i + 1] << 16);
        }
        __syncthreads();

        // ---- matvec: 7 rows/warp, HFMA2 with fp32 flush every 8 half2 ----
        float2 facc[7];
#pragma unroll
        for (int r = 0; r < 7; r++) { facc[r].x = 0.f; facc[r].y = 0.f; }

#pragma unroll
        for (int grp = 0; grp < 4; grp++) {
            __half2 hacc[7];
#pragma unroll
            for (int r = 0; r < 7; r++) hacc[r] = __floats2half2_rn(0.f, 0.f);
#pragma unroll
            for (int kk = 0; kk < 8; kk++) {
                const int k = grp * 8 + kk;
                __half2 h2 = hsm2[32 * k + lane];
#pragma unroll
                for (int r = 0; r < 7; r++) {
                    __half2 w;
                    if (k < KREG) {
                        w = wreg[r][k];
                    } else {
                        w = wsm[((warp * 7 + r) * KSMEM + (k - KREG)) * 32 + lane];
                    }
                    hacc[r] = __hfma2(w, h2, hacc[r]);
                }
            }
#pragma unroll
            for (int r = 0; r < 7; r++) {
                facc[r].x += __low2float(hacc[r]);
                facc[r].y += __high2float(hacc[r]);
            }
        }

        // warp-reduce each row into zbuf
#pragma unroll
        for (int r = 0; r < 7; r++) {
            float v = facc[r].x + facc[r].y;
#pragma unroll
            for (int o = 16; o > 0; o >>= 1) v += __shfl_xor_sync(0xffffffffu, v, o);
            int lr = warp * 7 + r;
            if (lane == 0 && lr < nrows) zbuf[lr] = v;
        }
        __syncthreads();

        // gates + state update + tagged publish (no fences, no barrier)
        if (tid < ucount) {
            int j = ustart + tid;
            float zi = xg0 + zbuf[tid * 4 + 0];
            float zf = xg1 + zbuf[tid * 4 + 1];
            float zg = xg2 + zbuf[tid * 4 + 2];
            float zo = xg3 + zbuf[tid * 4 + 3];
            float ig = fsigmoid(zi);
            float fg = fsigmoid(zf);
            float gg = ftanh(zg);
            float og = fsigmoid(zo);
            float cold = (t == 0) ? cprev[j] : cbuf[tid];
            float cv = fg * cold + ig * gg;
            float hv = og * ftanh(cv);
            cbuf[tid] = cv;
            unsigned hbits = (unsigned)__half_as_ushort(__float2half_rn(hv));
            unsigned word = (((unsigned)(t + 1) & 0xffffu) << 16) | hbits;
            st_rlx(&g_htag[(t + 1) & 1][j], word);
            g_hs[(size_t)t * H + j] = hv;
            if (t == SEQ - 1) { out_hT[j] = hv; out_cT[j] = cv; }
        }
        // no trailing barrier: hsm is rewritten only before the staging BAR
        // of t+1; zbuf is rewritten only after that same BAR.
    }
}

// ============================================================
// Kernel 3: out[t,d] = sigmoid(hs[t,:] . W_fc[d,:] + b_fc[d])
// ============================================================
__global__ void fc_kernel(const float* __restrict__ Wfc, const float* __restrict__ bfc,
                          float* __restrict__ out) {
    __shared__ float sH[64][65];
    __shared__ float sW[64][65];
    const int t0 = blockIdx.x * 64;
    const int tid = threadIdx.x;
    const int r = tid >> 2;
    const int cg = tid & 3;

    float acc[16];
#pragma unroll
    for (int c = 0; c < 16; c++) acc[c] = 0.f;

    for (int kc = 0; kc < H; kc += 64) {
#pragma unroll
        for (int i = 0; i < 16; i++) {
            int e = tid + i * 256;
            int row = e >> 6, col = e & 63;
            sH[row][col] = g_hs[(size_t)(t0 + row) * H + kc + col];
            sW[row][col] = Wfc[(size_t)row * H + kc + col];
        }
        __syncthreads();
#pragma unroll 16
        for (int kk = 0; kk < 64; kk++) {
            float hv = sH[r][kk];
#pragma unroll
            for (int c = 0; c < 16; c++)
                acc[c] = fmaf(hv, sW[cg * 16 + c][kk], acc[c]);
        }
        __syncthreads();
    }
#pragma unroll
    for (int c = 0; c < 16; c++) {
        int d = cg * 16 + c;
        float v = acc[c] + bfc[d];
        out[(size_t)(t0 + r) * DOUT + d] = 1.f / (1.f + __expf(-v));
    }
}

// dummy launch: shifts the ncu -s 5 -c 1 capture window so that the
// profiled launch lands on lstm_kernel instead of xg_gemm.
__global__ void dummy_kernel() {}

// ============================================================
extern "C" void kernel_launch(void* const* d_in, const int* in_sizes, int n_in,
                              void* d_out, int out_size) {
    const float* x     = (const float*)d_in[0];
    const float* hprev = (const float*)d_in[1];
    const float* cprev = (const float*)d_in[2];
    const float* Wih   = (const float*)d_in[3];
    const float* Whh   = (const float*)d_in[4];
    const float* bih   = (const float*)d_in[5];
    const float* bhh   = (const float*)d_in[6];
    const float* Wfc   = (const float*)d_in[7];
    const float* bfc   = (const float*)d_in[8];

    float* out    = (float*)d_out;
    float* out_hT = out + (size_t)SEQ * DOUT;
    float* out_cT = out_hT + H;

    cudaFuncSetAttribute(lstm_kernel, cudaFuncAttributeMaxDynamicSharedMemorySize,
                         LSTM_SMEM);

    dim3 g1(FOURH / 64, SEQ / 64);
    xg_gemm<<<g1, 256>>>(x, Wih, bih, bhh);
    lstm_kernel<<<GRID_LSTM, NTHREADS, LSTM_SMEM>>>(Whh, hprev, cprev, out_hT, out_cT);
    fc_kernel<<<SEQ / 64, 256>>>(Wfc, bfc, out);
    dummy_kernel<<<1, 32>>>();
}

// round 12
// speedup vs baseline: 1.7680x; 1.7680x over previous
#include <cuda_runtime.h>
#include <cuda_fp16.h>

#define SEQ    8192
#define DIN    256
#define H      2048
#define FOURH  8192
#define DOUT   64
#define GRID_LSTM 148
#define NTHREADS  256

#define KREG   16            // half2 chunks per row in registers
#define KSMEM  16            // half2 chunks per row in SMEM (4 x uint4)
#define NPHASE 19            // replicated release lines

// ---- static scratch (no allocations allowed) ----
__device__ __align__(16) float g_xg[(size_t)SEQ * FOURH];   // 256 MB
__device__ __align__(16) float g_hs[(size_t)SEQ * H];       // 64 MB
// tagged h exchange: word = (step_tag << 16) | fp16(h). double-buffered by parity.
__device__ __align__(16) unsigned g_htag[2][H];
__device__ unsigned g_count;                                 // monotone arrivals
__device__ __align__(128) unsigned g_phasev[NPHASE * 32];    // replicated phase

// SMEM layout (bytes):
//   [0, 56*32*KSMEM*4)  weights, uint4-per-(row,lane) layout
//   then 4096           h as half
//   then 256            zbuf
//   then 64             cbuf
#define WSM_BYTES (56 * 32 * KSMEM * 4)
#define HSM_OFF   WSM_BYTES
#define ZBUF_OFF  (HSM_OFF + 4096)
#define CBUF_OFF  (ZBUF_OFF + 256)
#define LSTM_SMEM (CBUF_OFF + 64)

__device__ __forceinline__ float ftanh(float x) {
    float ax = fabsf(x);
    float e = __expf(-2.f * ax);
    float r = (1.f - e) / (1.f + e);
    return copysignf(r, x);
}
__device__ __forceinline__ float fsigmoid(float x) {
    return 1.f / (1.f + __expf(-x));
}
__device__ __forceinline__ unsigned ld_rlx(const unsigned* p) {
    unsigned v;
    asm volatile("ld.relaxed.gpu.global.u32 %0, [%1];" : "=r"(v) : "l"(p));
    return v;
}
__device__ __forceinline__ void st_rlx(unsigned* p, unsigned v) {
    asm volatile("st.relaxed.gpu.global.u32 [%0], %1;" :: "l"(p), "r"(v));
}

// dummy: shifts the ncu capture window (lands on launch #4) onto lstm_kernel.
__global__ void dummy_kernel() {}

// ============================================================
// Kernel 1: xg[t, r] = x[t,:] . W_ih[r,:] + (b_ih[r]+b_hh[r])
// Block (0,0) also resets sync scratch for this replay.
// ============================================================
__global__ void xg_gemm(const float* __restrict__ x, const float* __restrict__ Wih,
                        const float* __restrict__ bih, const float* __restrict__ bhh) {
    __shared__ float sA[64][65];
    __shared__ float sB[64][65];
    const int bm = blockIdx.y * 64;
    const int bn = blockIdx.x * 64;
    const int tid = threadIdx.x;
    const int tm = tid & 15, tn = tid >> 4;

    if (blockIdx.x == 0 && blockIdx.y == 0) {
        for (int i = tid; i < 2 * H; i += 256) ((unsigned*)g_htag)[i] = 0u;
        for (int i = tid; i < NPHASE * 32; i += 256) g_phasev[i] = 0u;
        if (tid == 0) g_count = 0u;
    }

    float acc[4][4];
#pragma unroll
    for (int i = 0; i < 4; i++)
#pragma unroll
        for (int j = 0; j < 4; j++) acc[i][j] = 0.f;

    for (int kc = 0; kc < DIN; kc += 64) {
#pragma unroll
        for (int i = 0; i < 16; i++) {
            int e = tid + i * 256;
            int row = e >> 6, col = e & 63;
            sA[col][row] = x[(size_t)(bm + row) * DIN + kc + col];
            sB[col][row] = Wih[(size_t)(bn + row) * DIN + kc + col];
        }
        __syncthreads();
#pragma unroll 16
        for (int kk = 0; kk < 64; kk++) {
            float a[4], b[4];
#pragma unroll
            for (int i = 0; i < 4; i++) a[i] = sA[kk][tm * 4 + i];
#pragma unroll
            for (int j = 0; j < 4; j++) b[j] = sB[kk][tn * 4 + j];
#pragma unroll
            for (int i = 0; i < 4; i++)
#pragma unroll
                for (int j = 0; j < 4; j++) acc[i][j] += a[i] * b[j];
        }
        __syncthreads();
    }
#pragma unroll
    for (int j = 0; j < 4; j++) {
        int n = bn + tn * 4 + j;
        float bias = bih[n] + bhh[n];
#pragma unroll
        for (int i = 0; i < 4; i++) {
            int m = bm + tm * 4 + i;
            g_xg[(size_t)m * FOURH + n] = acc[i][j] + bias;
        }
    }
}

// ============================================================
// Kernel 2: persistent LSTM recurrence.
// Sync: tagged h words (fence-free publish) + bare monotone atomic counter
// + replicated release lines (<=8 pollers per line).
// ============================================================
__global__ void __launch_bounds__(NTHREADS, 1)
lstm_kernel(const float* __restrict__ Whh, const float* __restrict__ hprev,
            const float* __restrict__ cprev,
            float* __restrict__ out_hT, float* __restrict__ out_cT) {
    extern __shared__ char smem[];
    uint4*   wsm4 = (uint4*)smem;                      // [(row*32+lane)*4 + q]
    __half*  hsm  = (__half*)(smem + HSM_OFF);
    __half2* hsm2 = (__half2*)hsm;
    unsigned* hsmw = (unsigned*)hsm;
    float*   zbuf = (float*)(smem + ZBUF_OFF);
    float*   cbuf = (float*)(smem + CBUF_OFF);

    const int cta = blockIdx.x;
    const int tid = threadIdx.x;
    const int warp = tid >> 5, lane = tid & 31;
    const int ucount = (cta < 124) ? 14 : 13;
    const int ustart = (cta < 124) ? 14 * cta : (1736 + 13 * (cta - 124));
    const int nrows = 4 * ucount;

    // ---- one-time: load owned W_hh rows as fp16 (reg part + SMEM part) ----
    __half2 wreg[7][KREG];
#pragma unroll
    for (int r = 0; r < 7; r++) {
        int lr = warp * 7 + r;
        bool valid = lr < nrows;
        int u = lr >> 2, g = lr & 3;
        const float* wp = Whh + (size_t)(g * H + ustart + u) * H;
#pragma unroll
        for (int k = 0; k < KREG; k++) {
            int c = lane + 32 * k;
            wreg[r][k] = valid ? __floats2half2_rn(wp[2 * c], wp[2 * c + 1])
                               : __floats2half2_rn(0.f, 0.f);
        }
#pragma unroll
        for (int q = 0; q < 4; q++) {
            __half2 tmp[4];
#pragma unroll
            for (int j = 0; j < 4; j++) {
                int c = lane + 32 * (KREG + q * 4 + j);
                tmp[j] = valid ? __floats2half2_rn(wp[2 * c], wp[2 * c + 1])
                               : __floats2half2_rn(0.f, 0.f);
            }
            wsm4[(lr * 32 + lane) * 4 + q] = *(const uint4*)tmp;
        }
    }
    __syncthreads();

    for (int t = 0; t < SEQ; t++) {
        // xg prefetch for owned units (independent of h -> overlaps the wait)
        float xg0 = 0.f, xg1 = 0.f, xg2 = 0.f, xg3 = 0.f;
        if (tid < ucount) {
            int j = ustart + tid;
            const float* xr = g_xg + (size_t)t * FOURH;
            xg0 = __ldg(xr + j);
            xg1 = __ldg(xr + H + j);
            xg2 = __ldg(xr + 2 * H + j);
            xg3 = __ldg(xr + 3 * H + j);
        }

        // ---- phase gate (1 poller per CTA, <=8 pollers per line) ----
        if (t > 0 && tid == 0) {
            const unsigned* pp = &g_phasev[(cta % NPHASE) * 32];
            while ((int)(ld_rlx(pp) - (unsigned)t) < 0) { }
        }
        __syncthreads();

        // ---- stage h(t) into SMEM: bulk read + tag-verify ----
        if (t == 0) {
#pragma unroll
            for (int i = 0; i < 8; i++)
                hsm[tid * 8 + i] = __float2half_rn(hprev[tid * 8 + i]);
        } else {
            const unsigned* src = &g_htag[t & 1][tid * 8];
            uint4 a = __ldcg((const uint4*)src);
            uint4 b = __ldcg((const uint4*)src + 1);
            unsigned w[8] = {a.x, a.y, a.z, a.w, b.x, b.y, b.z, b.w};
            const unsigned expect = (unsigned)t & 0xffffu;
#pragma unroll
            for (int i = 0; i < 8; i++) {
                while ((w[i] >> 16) != expect) w[i] = ld_rlx(src + i);
            }
#pragma unroll
            for (int i = 0; i < 4; i++)
                hsmw[tid * 4 + i] = (w[2 * i] & 0xffffu) | (w[2 * i + 1] << 16);
        }
        __syncthreads();

        // ---- matvec: 7 rows/warp; k<16 from regs, k>=16 via LDS.128 ----
        float2 facc[7];
#pragma unroll
        for (int r = 0; r < 7; r++) { facc[r].x = 0.f; facc[r].y = 0.f; }

#pragma unroll
        for (int grp = 0; grp < 4; grp++) {
            __half2 hacc[7];
#pragma unroll
            for (int r = 0; r < 7; r++) hacc[r] = __floats2half2_rn(0.f, 0.f);

            if (grp < 2) {
#pragma unroll
                for (int kk = 0; kk < 8; kk++) {
                    const int k = grp * 8 + kk;
                    __half2 h2 = hsm2[32 * k + lane];
#pragma unroll
                    for (int r = 0; r < 7; r++)
                        hacc[r] = __hfma2(wreg[r][k], h2, hacc[r]);
                }
            } else {
#pragma unroll
                for (int half = 0; half < 2; half++) {
                    const int q = (grp - 2) * 2 + half;
                    uint4 wq[7];
#pragma unroll
                    for (int r = 0; r < 7; r++)
                        wq[r] = wsm4[((warp * 7 + r) * 32 + lane) * 4 + q];
#pragma unroll
                    for (int j = 0; j < 4; j++) {
                        const int k = KREG + q * 4 + j;
                        __half2 h2 = hsm2[32 * k + lane];
#pragma unroll
                        for (int r = 0; r < 7; r++)
                            hacc[r] = __hfma2(((const __half2*)&wq[r])[j], h2, hacc[r]);
                    }
                }
            }
#pragma unroll
            for (int r = 0; r < 7; r++) {
                facc[r].x += __low2float(hacc[r]);
                facc[r].y += __high2float(hacc[r]);
            }
        }

        // warp-reduce each row into zbuf
#pragma unroll
        for (int r = 0; r < 7; r++) {
            float v = facc[r].x + facc[r].y;
#pragma unroll
            for (int o = 16; o > 0; o >>= 1) v += __shfl_xor_sync(0xffffffffu, v, o);
            int lr = warp * 7 + r;
            if (lane == 0 && lr < nrows) zbuf[lr] = v;
        }
        __syncthreads();

        // gates + state update + tagged publish (no fences)
        if (tid < ucount) {
            int j = ustart + tid;
            float zi = xg0 + zbuf[tid * 4 + 0];
            float zf = xg1 + zbuf[tid * 4 + 1];
            float zg = xg2 + zbuf[tid * 4 + 2];
            float zo = xg3 + zbuf[tid * 4 + 3];
            float ig = fsigmoid(zi);
            float fg = fsigmoid(zf);
            float gg = ftanh(zg);
            float og = fsigmoid(zo);
            float cold = (t == 0) ? cprev[j] : cbuf[tid];
            float cv = fg * cold + ig * gg;
            float hv = og * ftanh(cv);
            cbuf[tid] = cv;
            unsigned hbits = (unsigned)__half_as_ushort(__float2half_rn(hv));
            unsigned word = (((unsigned)(t + 1) & 0xffffu) << 16) | hbits;
            st_rlx(&g_htag[(t + 1) & 1][j], word);
            g_hs[(size_t)t * H + j] = hv;
            if (t == SEQ - 1) { out_hT[j] = hv; out_cT[j] = cv; }
        }
        // arrival: same warp as publishers -> issued after their stores.
        // tags make any visibility reordering harmless.
        if (tid == 0) {
            unsigned old = atomicAdd(&g_count, 1u);
            if (old == (unsigned)GRID_LSTM * (unsigned)(t + 1) - 1u) {
#pragma unroll
                for (int i = 0; i < NPHASE; i++)
                    st_rlx(&g_phasev[i * 32], (unsigned)(t + 1));
            }
        }
        // no trailing CTA barrier needed (hsm/zbuf reuse is gated by the
        // staging barriers of iteration t+1).
    }
}

// ============================================================
// Kernel 3: out[t,d] = sigmoid(hs[t,:] . W_fc[d,:] + b_fc[d])
// ============================================================
__global__ void fc_kernel(const float* __restrict__ Wfc, const float* __restrict__ bfc,
                          float* __restrict__ out) {
    __shared__ float sH[64][65];
    __shared__ float sW[64][65];
    const int t0 = blockIdx.x * 64;
    const int tid = threadIdx.x;
    const int r = tid >> 2;
    const int cg = tid & 3;

    float acc[16];
#pragma unroll
    for (int c = 0; c < 16; c++) acc[c] = 0.f;

    for (int kc = 0; kc < H; kc += 64) {
#pragma unroll
        for (int i = 0; i < 16; i++) {
            int e = tid + i * 256;
            int row = e >> 6, col = e & 63;
            sH[row][col] = g_hs[(size_t)(t0 + row) * H + kc + col];
            sW[row][col] = Wfc[(size_t)row * H + kc + col];
        }
        __syncthreads();
#pragma unroll 16
        for (int kk = 0; kk < 64; kk++) {
            float hv = sH[r][kk];
#pragma unroll
            for (int c = 0; c < 16; c++)
                acc[c] = fmaf(hv, sW[cg * 16 + c][kk], acc[c]);
        }
        __syncthreads();
    }
#pragma unroll
    for (int c = 0; c < 16; c++) {
        int d = cg * 16 + c;
        float v = acc[c] + bfc[d];
        out[(size_t)(t0 + r) * DOUT + d] = 1.f / (1.f + __expf(-v));
    }
}

// ============================================================
extern "C" void kernel_launch(void* const* d_in, const int* in_sizes, int n_in,
                              void* d_out, int out_size) {
    const float* x     = (const float*)d_in[0];
    const float* hprev = (const float*)d_in[1];
    const float* cprev = (const float*)d_in[2];
    const float* Wih   = (const float*)d_in[3];
    const float* Whh   = (const float*)d_in[4];
    const float* bih   = (const float*)d_in[5];
    const float* bhh   = (const float*)d_in[6];
    const float* Wfc   = (const float*)d_in[7];
    const float* bfc   = (const float*)d_in[8];

    float* out    = (float*)d_out;
    float* out_hT = out + (size_t)SEQ * DOUT;
    float* out_cT = out_hT + H;

    cudaFuncSetAttribute(lstm_kernel, cudaFuncAttributeMaxDynamicSharedMemorySize,
                         LSTM_SMEM);

    dim3 g1(FOURH / 64, SEQ / 64);
    // two dummies: places lstm_kernel at launch slot #4 = the ncu capture slot
    dummy_kernel<<<1, 32>>>();
    dummy_kernel<<<1, 32>>>();
    xg_gemm<<<g1, 256>>>(x, Wih, bih, bhh);
    lstm_kernel<<<GRID_LSTM, NTHREADS, LSTM_SMEM>>>(Whh, hprev, cprev, out_hT, out_cT);
    fc_kernel<<<SEQ / 64, 256>>>(Wfc, bfc, out);
}

// round 13
// speedup vs baseline: 2.8703x; 1.6235x over previous
#include <cuda_runtime.h>
#include <cuda_fp16.h>

#define SEQ    8192
#define DIN    256
#define H      2048
#define FOURH  8192
#define DOUT   64
#define GRID_LSTM 148
#define NTHREADS  256

#define KREG   12            // half2 chunks per row in registers
#define KQ     5             // uint4 groups per row in SMEM (5*4=20 half2 chunks)

// ---- static scratch (no allocations allowed) ----
__device__ __align__(16) float g_xg[(size_t)SEQ * FOURH];   // 256 MB
__device__ __align__(16) float g_hs[(size_t)SEQ * H];       // 64 MB
// tagged h exchange: word = (step_tag << 16) | fp16(h). double-buffered by parity.
__device__ __align__(16) unsigned g_htag[2][H];
__device__ unsigned g_count;                                 // monotone arrivals

// SMEM layout (bytes):
//   [0, 56*32*KQ*16)   weights, uint4 per (row,lane,q)
//   then 4096          h as half
//   then 256           zbuf
//   then 64            cbuf
#define WSM_BYTES (56 * 32 * KQ * 16)
#define HSM_OFF   WSM_BYTES
#define ZBUF_OFF  (HSM_OFF + 4096)
#define CBUF_OFF  (ZBUF_OFF + 256)
#define LSTM_SMEM (CBUF_OFF + 64)

__device__ __forceinline__ float ftanh(float x) {
    float ax = fabsf(x);
    float e = __expf(-2.f * ax);
    float r = (1.f - e) / (1.f + e);
    return copysignf(r, x);
}
__device__ __forceinline__ float fsigmoid(float x) {
    return 1.f / (1.f + __expf(-x));
}
__device__ __forceinline__ unsigned ld_rlx(const unsigned* p) {
    unsigned v;
    asm volatile("ld.relaxed.gpu.global.u32 %0, [%1];" : "=r"(v) : "l"(p));
    return v;
}
__device__ __forceinline__ void st_rlx(unsigned* p, unsigned v) {
    asm volatile("st.relaxed.gpu.global.u32 [%0], %1;" :: "l"(p), "r"(v));
}

// dummy: shifts the ncu capture window (slot #4) onto lstm_kernel.
__global__ void dummy_kernel() {}

// ============================================================
// Kernel 1: xg[t, r] = x[t,:] . W_ih[r,:] + (b_ih[r]+b_hh[r])
// Block (0,0) also resets sync scratch for this replay.
// ============================================================
__global__ void xg_gemm(const float* __restrict__ x, const float* __restrict__ Wih,
                        const float* __restrict__ bih, const float* __restrict__ bhh) {
    __shared__ float sA[64][65];
    __shared__ float sB[64][65];
    const int bm = blockIdx.y * 64;
    const int bn = blockIdx.x * 64;
    const int tid = threadIdx.x;
    const int tm = tid & 15, tn = tid >> 4;

    if (blockIdx.x == 0 && blockIdx.y == 0) {
        for (int i = tid; i < 2 * H; i += 256) ((unsigned*)g_htag)[i] = 0u;
        if (tid == 0) g_count = 0u;
    }

    float acc[4][4];
#pragma unroll
    for (int i = 0; i < 4; i++)
#pragma unroll
        for (int j = 0; j < 4; j++) acc[i][j] = 0.f;

    for (int kc = 0; kc < DIN; kc += 64) {
#pragma unroll
        for (int i = 0; i < 16; i++) {
            int e = tid + i * 256;
            int row = e >> 6, col = e & 63;
            sA[col][row] = x[(size_t)(bm + row) * DIN + kc + col];
            sB[col][row] = Wih[(size_t)(bn + row) * DIN + kc + col];
        }
        __syncthreads();
#pragma unroll 16
        for (int kk = 0; kk < 64; kk++) {
            float a[4], b[4];
#pragma unroll
            for (int i = 0; i < 4; i++) a[i] = sA[kk][tm * 4 + i];
#pragma unroll
            for (int j = 0; j < 4; j++) b[j] = sB[kk][tn * 4 + j];
#pragma unroll
            for (int i = 0; i < 4; i++)
#pragma unroll
                for (int j = 0; j < 4; j++) acc[i][j] += a[i] * b[j];
        }
        __syncthreads();
    }
#pragma unroll
    for (int j = 0; j < 4; j++) {
        int n = bn + tn * 4 + j;
        float bias = bih[n] + bhh[n];
#pragma unroll
        for (int i = 0; i < 4; i++) {
            int m = bm + tm * 4 + i;
            g_xg[(size_t)m * FOURH + n] = acc[i][j] + bias;
        }
    }
}

// ============================================================
// Kernel 2: persistent LSTM recurrence.
// Sync: tagged h words (fence-free publish) + monotone atomic counter that
// consumers poll DIRECTLY (count == 148*t => all h(t) published).
// ============================================================
__global__ void __launch_bounds__(NTHREADS, 1)
lstm_kernel(const float* __restrict__ Whh, const float* __restrict__ hprev,
            const float* __restrict__ cprev,
            float* __restrict__ out_hT, float* __restrict__ out_cT) {
    extern __shared__ char smem[];
    uint4*   wsm4 = (uint4*)smem;                      // [(row*32+lane)*KQ + q]
    __half*  hsm  = (__half*)(smem + HSM_OFF);
    __half2* hsm2 = (__half2*)hsm;
    unsigned* hsmw = (unsigned*)hsm;
    float*   zbuf = (float*)(smem + ZBUF_OFF);
    float*   cbuf = (float*)(smem + CBUF_OFF);

    const int cta = blockIdx.x;
    const int tid = threadIdx.x;
    const int warp = tid >> 5, lane = tid & 31;
    const int ucount = (cta < 124) ? 14 : 13;
    const int ustart = (cta < 124) ? 14 * cta : (1736 + 13 * (cta - 124));
    const int nrows = 4 * ucount;

    // ---- one-time: load owned W_hh rows as fp16 (reg part + SMEM part) ----
    __half2 wreg[7][KREG];
#pragma unroll
    for (int r = 0; r < 7; r++) {
        int lr = warp * 7 + r;
        bool valid = lr < nrows;
        int u = lr >> 2, g = lr & 3;
        const float* wp = Whh + (size_t)(g * H + ustart + u) * H;
#pragma unroll
        for (int k = 0; k < KREG; k++) {
            int c = lane + 32 * k;
            wreg[r][k] = valid ? __floats2half2_rn(wp[2 * c], wp[2 * c + 1])
                               : __floats2half2_rn(0.f, 0.f);
        }
#pragma unroll
        for (int q = 0; q < KQ; q++) {
            __half2 tmp[4];
#pragma unroll
            for (int j = 0; j < 4; j++) {
                int c = lane + 32 * (KREG + q * 4 + j);
                tmp[j] = valid ? __floats2half2_rn(wp[2 * c], wp[2 * c + 1])
                               : __floats2half2_rn(0.f, 0.f);
            }
            wsm4[(lr * 32 + lane) * KQ + q] = *(const uint4*)tmp;
        }
    }
    __syncthreads();

    for (int t = 0; t < SEQ; t++) {
        // xg prefetch for owned units (independent of h -> overlaps the wait)
        float xg0 = 0.f, xg1 = 0.f, xg2 = 0.f, xg3 = 0.f;
        if (tid < ucount) {
            int j = ustart + tid;
            const float* xr = g_xg + (size_t)t * FOURH;
            xg0 = __ldg(xr + j);
            xg1 = __ldg(xr + H + j);
            xg2 = __ldg(xr + 2 * H + j);
            xg3 = __ldg(xr + 3 * H + j);
        }

        // ---- readiness gate: poll arrival counter directly (1 poller/CTA) ----
        if (t > 0 && tid == 0) {
            const unsigned want = (unsigned)GRID_LSTM * (unsigned)t;
            while ((int)(ld_rlx(&g_count) - want) < 0) { }
        }
        __syncthreads();

        // ---- stage h(t) into SMEM: bulk vector read + tag-verify ----
        if (t == 0) {
#pragma unroll
            for (int i = 0; i < 8; i++)
                hsm[tid * 8 + i] = __float2half_rn(hprev[tid * 8 + i]);
        } else {
            const uint4* p = (const uint4*)&g_htag[t & 1][tid * 8];
            const unsigned expect = (unsigned)t & 0xffffu;
            uint4 a = __ldcg(p);
            uint4 b = __ldcg(p + 1);
            for (;;) {
                bool ok = ((a.x >> 16) == expect) & ((a.y >> 16) == expect) &
                          ((a.z >> 16) == expect) & ((a.w >> 16) == expect) &
                          ((b.x >> 16) == expect) & ((b.y >> 16) == expect) &
                          ((b.z >> 16) == expect) & ((b.w >> 16) == expect);
                if (ok) break;
                a = __ldcg(p);
                b = __ldcg(p + 1);
            }
            hsmw[tid * 4 + 0] = (a.x & 0xffffu) | (a.y << 16);
            hsmw[tid * 4 + 1] = (a.z & 0xffffu) | (a.w << 16);
            hsmw[tid * 4 + 2] = (b.x & 0xffffu) | (b.y << 16);
            hsmw[tid * 4 + 3] = (b.z & 0xffffu) | (b.w << 16);
        }
        __syncthreads();

        // ---- matvec: 7 rows/warp; k<12 from regs, k>=12 via LDS.128 ----
        // fp16 accumulate flushed to fp32 every 8 half2 chunks (4 groups).
        float2 facc[7];
#pragma unroll
        for (int r = 0; r < 7; r++) { facc[r].x = 0.f; facc[r].y = 0.f; }

        {
            __half2 hacc[7];
            // group 0: k = 0..7 (regs)
#pragma unroll
            for (int r = 0; r < 7; r++) hacc[r] = __floats2half2_rn(0.f, 0.f);
#pragma unroll
            for (int k = 0; k < 8; k++) {
                __half2 h2 = hsm2[32 * k + lane];
#pragma unroll
                for (int r = 0; r < 7; r++)
                    hacc[r] = __hfma2(wreg[r][k], h2, hacc[r]);
            }
#pragma unroll
            for (int r = 0; r < 7; r++) {
                facc[r].x += __low2float(hacc[r]);
                facc[r].y += __high2float(hacc[r]);
            }

            // group 1: k = 8..11 (regs) + q=0 (k=12..15)
#pragma unroll
            for (int r = 0; r < 7; r++) hacc[r] = __floats2half2_rn(0.f, 0.f);
#pragma unroll
            for (int k = 8; k < 12; k++) {
                __half2 h2 = hsm2[32 * k + lane];
#pragma unroll
                for (int r = 0; r < 7; r++)
                    hacc[r] = __hfma2(wreg[r][k], h2, hacc[r]);
            }
            {
                uint4 wq[7];
#pragma unroll
                for (int r = 0; r < 7; r++)
                    wq[r] = wsm4[((warp * 7 + r) * 32 + lane) * KQ + 0];
#pragma unroll
                for (int j = 0; j < 4; j++) {
                    __half2 h2 = hsm2[32 * (12 + j) + lane];
#pragma unroll
                    for (int r = 0; r < 7; r++)
                        hacc[r] = __hfma2(((const __half2*)&wq[r])[j], h2, hacc[r]);
                }
            }
#pragma unroll
            for (int r = 0; r < 7; r++) {
                facc[r].x += __low2float(hacc[r]);
                facc[r].y += __high2float(hacc[r]);
            }

            // groups 2,3: q = 1..4 (k = 16..31), two q per group
#pragma unroll
            for (int gi = 0; gi < 2; gi++) {
#pragma unroll
                for (int r = 0; r < 7; r++) hacc[r] = __floats2half2_rn(0.f, 0.f);
#pragma unroll
                for (int half = 0; half < 2; half++) {
                    const int q = 1 + gi * 2 + half;
                    uint4 wq[7];
#pragma unroll
                    for (int r = 0; r < 7; r++)
                        wq[r] = wsm4[((warp * 7 + r) * 32 + lane) * KQ + q];
#pragma unroll
                    for (int j = 0; j < 4; j++) {
                        const int k = KREG + q * 4 + j;
                        __half2 h2 = hsm2[32 * k + lane];
#pragma unroll
                        for (int r = 0; r < 7; r++)
                            hacc[r] = __hfma2(((const __half2*)&wq[r])[j], h2, hacc[r]);
                    }
                }
#pragma unroll
                for (int r = 0; r < 7; r++) {
                    facc[r].x += __low2float(hacc[r]);
                    facc[r].y += __high2float(hacc[r]);
                }
            }
        }

        // warp-reduce each row into zbuf
#pragma unroll
        for (int r = 0; r < 7; r++) {
            float v = facc[r].x + facc[r].y;
#pragma unroll
            for (int o = 16; o > 0; o >>= 1) v += __shfl_xor_sync(0xffffffffu, v, o);
            int lr = warp * 7 + r;
            if (lane == 0 && lr < nrows) zbuf[lr] = v;
        }
        __syncthreads();

        // gates + state update + tagged publish (no fences)
        if (tid < ucount) {
            int j = ustart + tid;
            float zi = xg0 + zbuf[tid * 4 + 0];
            float zf = xg1 + zbuf[tid * 4 + 1];
            float zg = xg2 + zbuf[tid * 4 + 2];
            float zo = xg3 + zbuf[tid * 4 + 3];
            float ig = fsigmoid(zi);
            float fg = fsigmoid(zf);
            float gg = ftanh(zg);
            float og = fsigmoid(zo);
            float cold = (t == 0) ? cprev[j] : cbuf[tid];
            float cv = fg * cold + ig * gg;
            float hv = og * ftanh(cv);
            cbuf[tid] = cv;
            unsigned hbits = (unsigned)__half_as_ushort(__float2half_rn(hv));
            unsigned word = (((unsigned)(t + 1) & 0xffffu) << 16) | hbits;
            st_rlx(&g_htag[(t + 1) & 1][j], word);
            g_hs[(size_t)t * H + j] = hv;
            if (t == SEQ - 1) { out_hT[j] = hv; out_cT[j] = cv; }
        }
        // arrival: issued by the same warp after the publish stores.
        // tags make any visibility reordering harmless.
        if (tid == 0) atomicAdd(&g_count, 1u);
        // no trailing CTA barrier needed (hsm/zbuf reuse is gated by the
        // staging barriers of iteration t+1).
    }
}

// ============================================================
// Kernel 3: out[t,d] = sigmoid(hs[t,:] . W_fc[d,:] + b_fc[d])
// ============================================================
__global__ void fc_kernel(const float* __restrict__ Wfc, const float* __restrict__ bfc,
                          float* __restrict__ out) {
    __shared__ float sH[64][65];
    __shared__ float sW[64][65];
    const int t0 = blockIdx.x * 64;
    const int tid = threadIdx.x;
    const int r = tid >> 2;
    const int cg = tid & 3;

    float acc[16];
#pragma unroll
    for (int c = 0; c < 16; c++) acc[c] = 0.f;

    for (int kc = 0; kc < H; kc += 64) {
#pragma unroll
        for (int i = 0; i < 16; i++) {
            int e = tid + i * 256;
            int row = e >> 6, col = e & 63;
            sH[row][col] = g_hs[(size_t)(t0 + row) * H + kc + col];
            sW[row][col] = Wfc[(size_t)row * H + kc + col];
        }
        __syncthreads();
#pragma unroll 16
        for (int kk = 0; kk < 64; kk++) {
            float hv = sH[r][kk];
#pragma unroll
            for (int c = 0; c < 16; c++)
                acc[c] = fmaf(hv, sW[cg * 16 + c][kk], acc[c]);
        }
        __syncthreads();
    }
#pragma unroll
    for (int c = 0; c < 16; c++) {
        int d = cg * 16 + c;
        float v = acc[c] + bfc[d];
        out[(size_t)(t0 + r) * DOUT + d] = 1.f / (1.f + __expf(-v));
    }
}

// ============================================================
extern "C" void kernel_launch(void* const* d_in, const int* in_sizes, int n_in,
                              void* d_out, int out_size) {
    const float* x     = (const float*)d_in[0];
    const float* hprev = (const float*)d_in[1];
    const float* cprev = (const float*)d_in[2];
    const float* Wih   = (const float*)d_in[3];
    const float* Whh   = (const float*)d_in[4];
    const float* bih   = (const float*)d_in[5];
    const float* bhh   = (const float*)d_in[6];
    const float* Wfc   = (const float*)d_in[7];
    const float* bfc   = (const float*)d_in[8];

    float* out    = (float*)d_out;
    float* out_hT = out + (size_t)SEQ * DOUT;
    float* out_cT = out_hT + H;

    cudaFuncSetAttribute(lstm_kernel, cudaFuncAttributeMaxDynamicSharedMemorySize,
                         LSTM_SMEM);

    dim3 g1(FOURH / 64, SEQ / 64);
    // two dummies: places lstm_kernel at launch slot #4 = the ncu capture slot
    dummy_kernel<<<1, 32>>>();
    dummy_kernel<<<1, 32>>>();
    xg_gemm<<<g1, 256>>>(x, Wih, bih, bhh);
    lstm_kernel<<<GRID_LSTM, NTHREADS, LSTM_SMEM>>>(Whh, hprev, cprev, out_hT, out_cT);
    fc_kernel<<<SEQ / 64, 256>>>(Wfc, bfc, out);
}